// round 14
// baseline (speedup 1.0000x reference)
#include <cuda_runtime.h>
#include <math.h>

#define ZNUM  64
#define CELLS 64
#define C1    64
#define C2    32
#define BMAX  64

typedef unsigned long long ull;

// ---------- helpers ----------

__device__ __forceinline__ int read_dim(const void* p) {
    int   iv = ((const int*)p)[0];
    float fv = ((const float*)p)[0];
    bool int_ok = (iv >= 8 && iv <= 1000000);
    if (!int_ok && fv >= 8.f && fv <= 1.0e6f && floorf(fv) == fv) return (int)fv;
    return iv;
}

__device__ __forceinline__ int read_mask(const void* p, int idx, int layout) {
    if (layout == 0) return ((const int*)p)[idx] != 0;
    if (layout == 1) return ((const float*)p)[idx] != 0.0f;
    return ((const unsigned char*)p)[idx] != 0;
}

__device__ __forceinline__ void ffma2(ull& d, ull a, ull b) {
    asm("fma.rn.f32x2 %0, %1, %2, %0;" : "+l"(d) : "l"(a), "l"(b));
}
__device__ __forceinline__ void fadd2(ull& d, ull a) {
    asm("add.rn.f32x2 %0, %0, %1;" : "+l"(d) : "l"(a));
}
__device__ __forceinline__ ull pack2(float v) {
    ull r;
    asm("mov.b64 %0, {%1, %1};" : "=l"(r) : "f"(v));
    return r;
}

// ---------- fused kernel ----------
// grid (4, B): block = 8 oc = 4 f32x2 pairs.  256 threads = 8 warps:
//   warp w: pair = w & 3, ichalf = w >> 2.  lane owns cells {lane, lane+32}.
// Mainloop: 32 ic, software-pipelined (h depth-2, weights depth-1);
// 2-way ic reduction through aliased smem.
// launch_bounds(256, 1): grid-limited occupancy -> spend registers freely.

__global__ __launch_bounds__(256, 1)
void kFused(const float* __restrict__ hist,     // [B,Z,2]
            const void*  __restrict__ maskp,    // [B,Z]
            const int*   __restrict__ fr,       // [B,Z,4]
            const void*  __restrict__ Hp, const void* __restrict__ Wp,
            const float* __restrict__ w1,       // [C1,2]
            const float* __restrict__ b1,       // [C1]
            const float* __restrict__ w2,       // [C2,C1,3,3]
            const float* __restrict__ b2,       // [C2]
            float* __restrict__ out,            // [B,C2,64]
            int nwords)
{
    const int ocg = blockIdx.x;       // 0..3 -> oc base ocg*8
    const int b   = blockIdx.y;
    const int tid = threadIdx.x;

    __shared__ int   s_sy[ZNUM], s_sx[ZNUM], s_ey[ZNUM], s_ex[ZNUM];
    __shared__ float s_mv[ZNUM], s_vv[ZNUM];
    __shared__ int   s_mk[ZNUM];
    __shared__ float s_x[CELLS][2];
    // parallel-pooling combine buffers: [zg][cell]
    __shared__ float p_sm[4][CELLS], p_sv[4][CELLS];
    __shared__ unsigned char p_hit[4][CELLS], p_fb[4][CELLS];
    // blob: [0,16K) hs  [16K,36K) wpair ; after mainloop [0,18K) aliased as part
    __shared__ __align__(16) float blob[(16384 + 20480) / 4];

    float* hs    = blob;                          // [ic][cell], 16 KB
    float* wpair = blob + 4096;                   // [pair][ic][10 ull], 20 KB
    ull*   part  = (ull*)blob;                    // [t][pair][cell] ull (alias)

    const int H = read_dim(Hp);
    const int W = read_dim(Wp);

    // ---- mask layout detect (cooperative, bounded) ----
    int p_int = 1, p_float = 1;
    if (tid < 64) {
        const unsigned* mw = (const unsigned*)maskp;
        for (int i = 0; i < 4; ++i) {
            int idx = tid * 4 + i;
            if (idx < nwords) {
                unsigned v = mw[idx];
                if (v != 0u && v != 1u) p_int = 0;
                if (v != 0u && v != 0x3F800000u) p_float = 0;
            }
        }
    }
    if (tid < ZNUM) {
        const int z = tid;
        const int* bx = fr + ((long)b * ZNUM + z) * 4;
        s_sy[z] = max(bx[0], 0);
        s_sx[z] = max(bx[1], 0);
        s_ey[z] = min(bx[2], H);
        s_ex[z] = min(bx[3], W);
        s_mv[z] = hist[((long)b * ZNUM + z) * 2 + 0];
        s_vv[z] = hist[((long)b * ZNUM + z) * 2 + 1];
    }
    int all_int   = __syncthreads_and(p_int);
    int all_float = __syncthreads_and(p_float);
    const int mlayout = all_int ? 0 : (all_float ? 1 : 2);
    if (tid < ZNUM)
        s_mk[tid] = read_mask(maskp, b * ZNUM + tid, mlayout);

    // ---- stage weight pairs (no divides): item -> (p, s, ic) ----
    const int oc0 = ocg * 8;
    {
#pragma unroll
        for (int k = 0; k < 2; ++k) {
            const int item = tid + k * 256;
            const int p  = item >> 7;            // 0..3
            const int s  = (item >> 6) & 1;      // 0..1
            const int ic = item & 63;
            const float* src = w2 + (oc0 + 2 * p + s) * 576 + ic * 9;
            float* dst = wpair + (p * 64 + ic) * 20 + s;
#pragma unroll
            for (int t = 0; t < 9; ++t) dst[2 * t] = src[t];
        }
    }
    __syncthreads();

    // ---- pooling: parallel over 4 z-groups of 16 (descending scan) ----
    const int bh = H / 8, bw = W / 8;
    const float inv_area = 1.0f / (float)(bh * bw);
    const float area = (float)(bh * bw);

    {
        const int cell = tid & 63;
        const int zg   = tid >> 6;               // 0..3
        const int r = cell >> 3, c = cell & 7;
        const int cy0 = r * bh, cy1 = cy0 + bh;
        const int cx0 = c * bw, cx1 = cx0 + bw;

        float sm = 0.f, sv = 0.f;
        unsigned char hit = 0, fbl = 0;
        for (int z = zg * 16 + 15; z >= zg * 16; --z) {
            if (!s_mk[z]) continue;
            int iy0 = max(s_sy[z], cy0), iy1 = min(s_ey[z], cy1);
            int ix0 = max(s_sx[z], cx0), ix1 = min(s_ex[z], cx1);
            if (iy0 >= iy1 || ix0 >= ix1) continue;
            if (iy0 == cy0 && iy1 == cy1 && ix0 == cx0 && ix1 == cx1) {
                sm = s_mv[z] * area;
                sv = s_vv[z] * area;
            } else {
                fbl = 1;   // partial cover -> exact per-pixel fallback later
            }
            hit = 1;
            break;
        }
        p_sm[zg][cell] = sm;  p_sv[zg][cell] = sv;
        p_hit[zg][cell] = hit; p_fb[zg][cell] = fbl;
    }
    __syncthreads();

    if (tid < CELLS) {
        const int r = tid >> 3, c = tid & 7;
        const int cy0 = r * bh, cy1 = cy0 + bh;
        const int cx0 = c * bw, cx1 = cx0 + bw;

        float sm = 0.f, sv = 0.f;
        int fb = 0;
#pragma unroll
        for (int zg = 3; zg >= 0; --zg) {        // highest group wins (LWW)
            if (p_hit[zg][tid]) {
                sm = p_sm[zg][tid]; sv = p_sv[zg][tid]; fb = p_fb[zg][tid];
                break;
            }
        }
        if (fb) {                                 // exact per-pixel fallback
            sm = 0.f; sv = 0.f;
            for (int y = cy0; y < cy1; ++y)
                for (int x = cx0; x < cx1; ++x)
                    for (int z = ZNUM - 1; z >= 0; --z) {
                        if (!s_mk[z]) continue;
                        if (y >= s_sy[z] && y < s_ey[z] &&
                            x >= s_sx[z] && x < s_ex[z]) {
                            sm += s_mv[z]; sv += s_vv[z];
                            break;
                        }
                    }
        }
        float tm = sm * inv_area, tv = sv * inv_area;
        s_x[tid][0] = log1pf(fmaxf(tm, 0.f));
        s_x[tid][1] = log1pf(fmaxf(tv, 0.f));
    }
    __syncthreads();

    // ---- 1x1 conv (2 -> C1) + SiLU into hs ----
#pragma unroll
    for (int k = 0; k < 16; ++k) {
        const int i = tid + k * 256;
        const int ch = i >> 6, cell = i & 63;
        float v = fmaf(w1[ch * 2 + 0], s_x[cell][0],
                  fmaf(w1[ch * 2 + 1], s_x[cell][1], b1[ch]));
        hs[i] = v * __fdividef(1.0f, 1.0f + __expf(-v));
    }
    __syncthreads();

    // ---- mainloop: 9-tap GEMM over 32 ic per warp, software-pipelined ----
    const int w      = tid >> 5;
    const int lane   = tid & 31;
    const int pair   = w & 3;
    const int ichalf = w >> 2;

    ull a0[9], a1[9];
#pragma unroll
    for (int t = 0; t < 9; ++t) { a0[t] = 0; a1[t] = 0; }

    {
        const int    icb = ichalf * 32;
        const float* hp  = hs + icb * 64 + lane;
        const float* qp  = wpair + pair * 1280 + icb * 20;

        // h prefetch: depth 2; weights: depth 1
        float h0a = hp[0],  h1a = hp[32];
        float h0b = hp[64], h1b = hp[96];
        ulonglong2 w01 = *(const ulonglong2*)(qp);
        ulonglong2 w23 = *(const ulonglong2*)(qp + 4);
        ulonglong2 w45 = *(const ulonglong2*)(qp + 8);
        ulonglong2 w67 = *(const ulonglong2*)(qp + 12);
        ull        w8  = *(const ull*)(qp + 16);

#pragma unroll
        for (int ii = 0; ii < 32; ++ii) {
            const ull H0 = pack2(h0a);
            const ull H1 = pack2(h1a);
            const ulonglong2 c01 = w01, c23 = w23, c45 = w45, c67 = w67;
            const ull        c8  = w8;
            // rotate h window; fetch ii+2
            h0a = h0b; h1a = h1b;
            if (ii < 30) {
                h0b = hp[(ii + 2) * 64];
                h1b = hp[(ii + 2) * 64 + 32];
            }
            // fetch next weights (ii+1)
            if (ii < 31) {
                const float* qn = qp + (ii + 1) * 20;
                w01 = *(const ulonglong2*)(qn);
                w23 = *(const ulonglong2*)(qn + 4);
                w45 = *(const ulonglong2*)(qn + 8);
                w67 = *(const ulonglong2*)(qn + 12);
                w8  = *(const ull*)(qn + 16);
            }
            ffma2(a0[0], c01.x, H0);  ffma2(a1[0], c01.x, H1);
            ffma2(a0[1], c01.y, H0);  ffma2(a1[1], c01.y, H1);
            ffma2(a0[2], c23.x, H0);  ffma2(a1[2], c23.x, H1);
            ffma2(a0[3], c23.y, H0);  ffma2(a1[3], c23.y, H1);
            ffma2(a0[4], c45.x, H0);  ffma2(a1[4], c45.x, H1);
            ffma2(a0[5], c45.y, H0);  ffma2(a1[5], c45.y, H1);
            ffma2(a0[6], c67.x, H0);  ffma2(a1[6], c67.x, H1);
            ffma2(a0[7], c67.y, H0);  ffma2(a1[7], c67.y, H1);
            ffma2(a0[8], c8,    H0);  ffma2(a1[8], c8,    H1);
        }
    }

    __syncthreads();   // hs + wpair dead -> part may alias

    // ---- 2 -> 1 reduction: ichalf 1 spills, ichalf 0 adds + writes final ----
    if (ichalf == 1) {
#pragma unroll
        for (int t = 0; t < 9; ++t) {
            ull* dst = part + (t * 4 + pair) * 64;
            dst[lane]      = a0[t];
            dst[32 + lane] = a1[t];
        }
    }
    __syncthreads();
    if (ichalf == 0) {
#pragma unroll
        for (int t = 0; t < 9; ++t) {
            ull* dst = part + (t * 4 + pair) * 64;
            fadd2(a0[t], dst[lane]);
            fadd2(a1[t], dst[32 + lane]);
            dst[lane]      = a0[t];
            dst[32 + lane] = a1[t];
        }
    }
    __syncthreads();

    // ---- epilogue: 9-tap shift-add; 2 outputs per thread ----
    {
        const float* U = (const float*)part;
#pragma unroll
        for (int r = 0; r < 2; ++r) {
            const int j    = tid + r * 256;      // 0..511
            const int oc_l = j >> 6;             // 0..7
            const int cell = j & 63;
            const int pr   = oc_l >> 1;
            const int s    = oc_l & 1;
            const int y = cell >> 3, x = cell & 7;
            float sum = b2[oc0 + oc_l];
#pragma unroll
            for (int t = 0; t < 9; ++t) {
                const int yy = y + t / 3 - 1;
                const int xx = x + t % 3 - 1;
                if (yy >= 0 && yy < 8 && xx >= 0 && xx < 8)
                    sum += U[((t * 4 + pr) * 64 + yy * 8 + xx) * 2 + s];
            }
            out[((long)b * C2 + oc0 + oc_l) * 64 + cell] = sum;
        }
    }
}

// ---------- launch ----------

extern "C" void kernel_launch(void* const* d_in, const int* in_sizes, int n_in,
                              void* d_out, int out_size)
{
    // input order: hist_BZ2, mask_BZ, fr_BZ4, H, W, w1, b1, w2, b2
    const float* hist  = (const float*)d_in[0];
    const void*  maskp = d_in[1];
    const int*   fr    = (const int*)d_in[2];
    const void*  Hp    = d_in[3];
    const void*  Wp    = d_in[4];
    const float* w1    = (const float*)d_in[5];
    const float* b1    = (const float*)d_in[6];
    const float* w2    = (const float*)d_in[7];
    const float* b2    = (const float*)d_in[8];
    float* out = (float*)d_out;

    int B = in_sizes[1] / ZNUM;
    if (B < 1) B = 1;
    if (B > BMAX) B = BMAX;

    int nwords = in_sizes[1] / 4;
    if (nwords > 256) nwords = 256;
    if (nwords < 1) nwords = 1;

    kFused<<<dim3(4, B), 256>>>(hist, maskp, fr, Hp, Wp,
                                w1, b1, w2, b2, out, nwords);
}

// round 15
// speedup vs baseline: 1.0201x; 1.0201x over previous
#include <cuda_runtime.h>
#include <math.h>

#define ZNUM  64
#define CELLS 64
#define C1    64
#define C2    32
#define BMAX  64

typedef unsigned long long ull;

// ---------- helpers ----------

__device__ __forceinline__ int read_dim(const void* p) {
    int   iv = ((const int*)p)[0];
    float fv = ((const float*)p)[0];
    bool int_ok = (iv >= 8 && iv <= 1000000);
    if (!int_ok && fv >= 8.f && fv <= 1.0e6f && floorf(fv) == fv) return (int)fv;
    return iv;
}

__device__ __forceinline__ int read_mask(const void* p, int idx, int layout) {
    if (layout == 0) return ((const int*)p)[idx] != 0;
    if (layout == 1) return ((const float*)p)[idx] != 0.0f;
    return ((const unsigned char*)p)[idx] != 0;
}

__device__ __forceinline__ void ffma2(ull& d, ull a, ull b) {
    asm("fma.rn.f32x2 %0, %1, %2, %0;" : "+l"(d) : "l"(a), "l"(b));
}
__device__ __forceinline__ void fadd2(ull& d, ull a) {
    asm("add.rn.f32x2 %0, %0, %1;" : "+l"(d) : "l"(a));
}
__device__ __forceinline__ ull pack2(float v) {
    ull r;
    asm("mov.b64 %0, {%1, %1};" : "=l"(r) : "f"(v));
    return r;
}

// ---------- fused kernel ----------
// grid (2, B) = 128 blocks -> ONE wave on 148 SMs (no wave quantization).
// block = 16 oc = 8 f32x2 pairs. 512 threads = 16 warps:
//   warp w: pair = w & 7, ichalf = w >> 3.  lane owns cells {lane, lane+32}.
// Mainloop: 32 ic, software-pipelined; 2-way ic reduction through aliased smem.
// Dynamic smem blob: [0,16K) hs | [16K,56K) wpair ; after mainloop
// [0,36K) aliased as part.

__global__ __launch_bounds__(512, 1)
void kFused(const float* __restrict__ hist,     // [B,Z,2]
            const void*  __restrict__ maskp,    // [B,Z]
            const int*   __restrict__ fr,       // [B,Z,4]
            const void*  __restrict__ Hp, const void* __restrict__ Wp,
            const float* __restrict__ w1,       // [C1,2]
            const float* __restrict__ b1,       // [C1]
            const float* __restrict__ w2,       // [C2,C1,3,3]
            const float* __restrict__ b2,       // [C2]
            float* __restrict__ out,            // [B,C2,64]
            int nwords)
{
    const int ocg = blockIdx.x;       // 0..1 -> oc base ocg*16
    const int b   = blockIdx.y;
    const int tid = threadIdx.x;

    __shared__ int   s_sy[ZNUM], s_sx[ZNUM], s_ey[ZNUM], s_ex[ZNUM];
    __shared__ float s_mv[ZNUM], s_vv[ZNUM];
    __shared__ int   s_mk[ZNUM];
    __shared__ float s_x[CELLS][2];
    __shared__ float p_sm[4][CELLS], p_sv[4][CELLS];
    __shared__ unsigned char p_hit[4][CELLS], p_fb[4][CELLS];

    extern __shared__ __align__(16) float blob[];   // 57344 B dynamic
    float* hs    = blob;                 // [ic][cell], 16 KB
    float* wpair = blob + 4096;          // [pair][ic][10 ull], 40 KB
    ull*   part  = (ull*)blob;           // [t][pair][cell] ull, 36 KB (alias)

    const int H = read_dim(Hp);
    const int W = read_dim(Wp);

    // ---- mask layout detect (cooperative, bounded) ----
    int p_int = 1, p_float = 1;
    if (tid < 64) {
        const unsigned* mw = (const unsigned*)maskp;
        for (int i = 0; i < 4; ++i) {
            int idx = tid * 4 + i;
            if (idx < nwords) {
                unsigned v = mw[idx];
                if (v != 0u && v != 1u) p_int = 0;
                if (v != 0u && v != 0x3F800000u) p_float = 0;
            }
        }
    }
    if (tid < ZNUM) {
        const int z = tid;
        const int* bx = fr + ((long)b * ZNUM + z) * 4;
        s_sy[z] = max(bx[0], 0);
        s_sx[z] = max(bx[1], 0);
        s_ey[z] = min(bx[2], H);
        s_ex[z] = min(bx[3], W);
        s_mv[z] = hist[((long)b * ZNUM + z) * 2 + 0];
        s_vv[z] = hist[((long)b * ZNUM + z) * 2 + 1];
    }
    int all_int   = __syncthreads_and(p_int);
    int all_float = __syncthreads_and(p_float);
    const int mlayout = all_int ? 0 : (all_float ? 1 : 2);
    if (tid < ZNUM)
        s_mk[tid] = read_mask(maskp, b * ZNUM + tid, mlayout);

    // ---- stage weight pairs (no divides): item -> (p, s, ic) ----
    const int oc0 = ocg * 16;
    {
        // 8 pairs x 2 sides x 64 ic = 1024 items; 2 per thread
#pragma unroll
        for (int k = 0; k < 2; ++k) {
            const int item = tid + k * 512;
            const int p  = item >> 7;            // 0..7
            const int s  = (item >> 6) & 1;      // 0..1
            const int ic = item & 63;
            const float* src = w2 + (oc0 + 2 * p + s) * 576 + ic * 9;
            float* dst = wpair + (p * 64 + ic) * 20 + s;
#pragma unroll
            for (int t = 0; t < 9; ++t) dst[2 * t] = src[t];
        }
    }
    __syncthreads();

    // ---- pooling: parallel over 4 z-groups of 16 (descending scan) ----
    const int bh = H / 8, bw = W / 8;
    const float inv_area = 1.0f / (float)(bh * bw);
    const float area = (float)(bh * bw);

    if (tid < 256) {
        const int cell = tid & 63;
        const int zg   = tid >> 6;               // 0..3
        const int r = cell >> 3, c = cell & 7;
        const int cy0 = r * bh, cy1 = cy0 + bh;
        const int cx0 = c * bw, cx1 = cx0 + bw;

        float sm = 0.f, sv = 0.f;
        unsigned char hit = 0, fbl = 0;
        for (int z = zg * 16 + 15; z >= zg * 16; --z) {
            if (!s_mk[z]) continue;
            int iy0 = max(s_sy[z], cy0), iy1 = min(s_ey[z], cy1);
            int ix0 = max(s_sx[z], cx0), ix1 = min(s_ex[z], cx1);
            if (iy0 >= iy1 || ix0 >= ix1) continue;
            if (iy0 == cy0 && iy1 == cy1 && ix0 == cx0 && ix1 == cx1) {
                sm = s_mv[z] * area;
                sv = s_vv[z] * area;
            } else {
                fbl = 1;   // partial cover -> exact per-pixel fallback later
            }
            hit = 1;
            break;
        }
        p_sm[zg][cell] = sm;  p_sv[zg][cell] = sv;
        p_hit[zg][cell] = hit; p_fb[zg][cell] = fbl;
    }
    __syncthreads();

    if (tid < CELLS) {
        const int r = tid >> 3, c = tid & 7;
        const int cy0 = r * bh, cy1 = cy0 + bh;
        const int cx0 = c * bw, cx1 = cx0 + bw;

        float sm = 0.f, sv = 0.f;
        int fb = 0;
#pragma unroll
        for (int zg = 3; zg >= 0; --zg) {        // highest group wins (LWW)
            if (p_hit[zg][tid]) {
                sm = p_sm[zg][tid]; sv = p_sv[zg][tid]; fb = p_fb[zg][tid];
                break;
            }
        }
        if (fb) {                                 // exact per-pixel fallback
            sm = 0.f; sv = 0.f;
            for (int y = cy0; y < cy1; ++y)
                for (int x = cx0; x < cx1; ++x)
                    for (int z = ZNUM - 1; z >= 0; --z) {
                        if (!s_mk[z]) continue;
                        if (y >= s_sy[z] && y < s_ey[z] &&
                            x >= s_sx[z] && x < s_ex[z]) {
                            sm += s_mv[z]; sv += s_vv[z];
                            break;
                        }
                    }
        }
        float tm = sm * inv_area, tv = sv * inv_area;
        s_x[tid][0] = log1pf(fmaxf(tm, 0.f));
        s_x[tid][1] = log1pf(fmaxf(tv, 0.f));
    }
    __syncthreads();

    // ---- 1x1 conv (2 -> C1) + SiLU into hs ----
#pragma unroll
    for (int k = 0; k < 8; ++k) {
        const int i = tid + k * 512;
        const int ch = i >> 6, cell = i & 63;
        float v = fmaf(w1[ch * 2 + 0], s_x[cell][0],
                  fmaf(w1[ch * 2 + 1], s_x[cell][1], b1[ch]));
        hs[i] = v * __fdividef(1.0f, 1.0f + __expf(-v));
    }
    __syncthreads();

    // ---- mainloop: 9-tap GEMM over 32 ic per warp, software-pipelined ----
    const int w      = tid >> 5;
    const int lane   = tid & 31;
    const int pair   = w & 7;
    const int ichalf = w >> 3;

    ull a0[9], a1[9];
#pragma unroll
    for (int t = 0; t < 9; ++t) { a0[t] = 0; a1[t] = 0; }

    {
        const int    icb = ichalf * 32;
        const float* hp  = hs + icb * 64 + lane;
        const float* qp  = wpair + pair * 1280 + icb * 20;

        // h prefetch: depth 2; weights: depth 1
        float h0a = hp[0],  h1a = hp[32];
        float h0b = hp[64], h1b = hp[96];
        ulonglong2 w01 = *(const ulonglong2*)(qp);
        ulonglong2 w23 = *(const ulonglong2*)(qp + 4);
        ulonglong2 w45 = *(const ulonglong2*)(qp + 8);
        ulonglong2 w67 = *(const ulonglong2*)(qp + 12);
        ull        w8  = *(const ull*)(qp + 16);

#pragma unroll
        for (int ii = 0; ii < 32; ++ii) {
            const ull H0 = pack2(h0a);
            const ull H1 = pack2(h1a);
            const ulonglong2 c01 = w01, c23 = w23, c45 = w45, c67 = w67;
            const ull        c8  = w8;
            h0a = h0b; h1a = h1b;
            if (ii < 30) {
                h0b = hp[(ii + 2) * 64];
                h1b = hp[(ii + 2) * 64 + 32];
            }
            if (ii < 31) {
                const float* qn = qp + (ii + 1) * 20;
                w01 = *(const ulonglong2*)(qn);
                w23 = *(const ulonglong2*)(qn + 4);
                w45 = *(const ulonglong2*)(qn + 8);
                w67 = *(const ulonglong2*)(qn + 12);
                w8  = *(const ull*)(qn + 16);
            }
            ffma2(a0[0], c01.x, H0);  ffma2(a1[0], c01.x, H1);
            ffma2(a0[1], c01.y, H0);  ffma2(a1[1], c01.y, H1);
            ffma2(a0[2], c23.x, H0);  ffma2(a1[2], c23.x, H1);
            ffma2(a0[3], c23.y, H0);  ffma2(a1[3], c23.y, H1);
            ffma2(a0[4], c45.x, H0);  ffma2(a1[4], c45.x, H1);
            ffma2(a0[5], c45.y, H0);  ffma2(a1[5], c45.y, H1);
            ffma2(a0[6], c67.x, H0);  ffma2(a1[6], c67.x, H1);
            ffma2(a0[7], c67.y, H0);  ffma2(a1[7], c67.y, H1);
            ffma2(a0[8], c8,    H0);  ffma2(a1[8], c8,    H1);
        }
    }

    __syncthreads();   // hs + wpair dead -> part may alias

    // ---- 2 -> 1 reduction: ichalf 1 spills, ichalf 0 adds + writes final ----
    if (ichalf == 1) {
#pragma unroll
        for (int t = 0; t < 9; ++t) {
            ull* dst = part + (t * 8 + pair) * 64;
            dst[lane]      = a0[t];
            dst[32 + lane] = a1[t];
        }
    }
    __syncthreads();
    if (ichalf == 0) {
#pragma unroll
        for (int t = 0; t < 9; ++t) {
            ull* dst = part + (t * 8 + pair) * 64;
            fadd2(a0[t], dst[lane]);
            fadd2(a1[t], dst[32 + lane]);
            dst[lane]      = a0[t];
            dst[32 + lane] = a1[t];
        }
    }
    __syncthreads();

    // ---- epilogue: 9-tap shift-add; 2 outputs per thread ----
    {
        const float* U = (const float*)part;
#pragma unroll
        for (int r = 0; r < 2; ++r) {
            const int j    = tid + r * 512;      // 0..1023
            const int oc_l = j >> 6;             // 0..15
            const int cell = j & 63;
            const int pr   = oc_l >> 1;
            const int s    = oc_l & 1;
            const int y = cell >> 3, x = cell & 7;
            float sum = b2[oc0 + oc_l];
#pragma unroll
            for (int t = 0; t < 9; ++t) {
                const int yy = y + t / 3 - 1;
                const int xx = x + t % 3 - 1;
                if (yy >= 0 && yy < 8 && xx >= 0 && xx < 8)
                    sum += U[((t * 8 + pr) * 64 + yy * 8 + xx) * 2 + s];
            }
            out[((long)b * C2 + oc0 + oc_l) * 64 + cell] = sum;
        }
    }
}

// ---------- launch ----------

#define DYN_SMEM 57344

extern "C" void kernel_launch(void* const* d_in, const int* in_sizes, int n_in,
                              void* d_out, int out_size)
{
    // input order: hist_BZ2, mask_BZ, fr_BZ4, H, W, w1, b1, w2, b2
    const float* hist  = (const float*)d_in[0];
    const void*  maskp = d_in[1];
    const int*   fr    = (const int*)d_in[2];
    const void*  Hp    = d_in[3];
    const void*  Wp    = d_in[4];
    const float* w1    = (const float*)d_in[5];
    const float* b1    = (const float*)d_in[6];
    const float* w2    = (const float*)d_in[7];
    const float* b2    = (const float*)d_in[8];
    float* out = (float*)d_out;

    int B = in_sizes[1] / ZNUM;
    if (B < 1) B = 1;
    if (B > BMAX) B = BMAX;

    int nwords = in_sizes[1] / 4;
    if (nwords > 256) nwords = 256;
    if (nwords < 1) nwords = 1;

    cudaFuncSetAttribute(kFused, cudaFuncAttributeMaxDynamicSharedMemorySize,
                         DYN_SMEM);

    kFused<<<dim3(2, B), 512, DYN_SMEM>>>(hist, maskp, fr, Hp, Wp,
                                          w1, b1, w2, b2, out, nwords);
}